// round 11
// baseline (speedup 1.0000x reference)
#include <cuda_runtime.h>
#include <cuda_bf16.h>
#include <cstdint>

#define D 128
#define MAXN 100000
#define MAXE 1600000

// ---------------- device scratch (allocation-free rule) --------------------
__device__ float g_agg[(size_t)MAXN * D];
__device__ float g_t  [(size_t)MAXN * D];
// CSR scratch
__device__ int g_cnt[MAXN];
__device__ int g_off[MAXN + 1];
__device__ int g_cur[MAXN];
__device__ int g_csr[MAXE];
__device__ int g_bsum[128];
__device__ int g_bbase[128];
// 6 GEMMs x (hi + lo) W^T images, padded row-major [n][136] bf16
#define IMG_ELEMS 17408            // 128 * 136
__device__ __nv_bfloat16 g_Wimg[6 * 2 * IMG_ELEMS];

// ---------------- smem layout for fused layer kernel (bytes) ----------------
#define ROWB   272                 // 136 bf16 per row
#define HALF   34816               // hi->lo delta within an image (128*272)
#define OFF_W1    0                // W1 hi+lo (69632)
#define OFF_W2    69632            // W2 hi+lo (69632)
#define OFF_AHI   139264           // A / h image hi (34816)
#define OFF_ALO   174080           // A / h image lo (34816)
#define OFF_B1    208896
#define OFF_B2    209408
#define SMEM_TOTAL 209920

__device__ __forceinline__ uint32_t smem_u32(const void* p) {
    uint32_t a;
    asm("{ .reg .u64 t; cvta.to.shared.u64 t, %1; cvt.u32.u64 %0, t; }" : "=r"(a) : "l"(p));
    return a;
}

#define LDSM_X4(r0, r1, r2, r3, addr) \
    asm volatile("ldmatrix.sync.aligned.m8n8.x4.shared.b16 {%0,%1,%2,%3}, [%4];" \
                 : "=r"(r0), "=r"(r1), "=r"(r2), "=r"(r3) : "r"(addr))

#define CP_ASYNC16(dst, src) \
    asm volatile("cp.async.cg.shared.global [%0], [%1], 16;" :: "r"(dst), "l"(src))
#define CP_WAIT() asm volatile("cp.async.wait_all;" ::: "memory")

__device__ __forceinline__ void mma_bf16(float* c, const uint32_t* a, uint32_t b0, uint32_t b1) {
    asm volatile(
        "mma.sync.aligned.m16n8k16.row.col.f32.bf16.bf16.f32 "
        "{%0,%1,%2,%3}, {%4,%5,%6,%7}, {%8,%9}, {%0,%1,%2,%3};"
        : "+f"(c[0]), "+f"(c[1]), "+f"(c[2]), "+f"(c[3])
        : "r"(a[0]), "r"(a[1]), "r"(a[2]), "r"(a[3]), "r"(b0), "r"(b1));
}

// hi/lo bf16 split of 2 floats -> packed bf16x2 regs
__device__ __forceinline__ void split2(float x0, float x1, uint32_t& hi, uint32_t& lo) {
    __nv_bfloat162 h = __floats2bfloat162_rn(x0, x1);
    float r0 = x0 - __bfloat162float(h.x);
    float r1 = x1 - __bfloat162float(h.y);
    __nv_bfloat162 l = __floats2bfloat162_rn(r0, r1);
    hi = *reinterpret_cast<uint32_t*>(&h);
    lo = *reinterpret_cast<uint32_t*>(&l);
}

// ================= CSR build =================================================
__global__ void zero_cnt_kernel(int* cnt, int N) {
    int i = blockIdx.x * blockDim.x + threadIdx.x;
    if (i < N) cnt[i] = 0;
}

__global__ void hist_kernel(const int* __restrict__ ei, int* cnt, int E) {
    int e = blockIdx.x * blockDim.x + threadIdx.x;
    if (e < E) atomicAdd(&cnt[ei[E + e]], 1);
}

__global__ void scan1_kernel(const int* __restrict__ cnt, int* bsum, int N) {
    __shared__ int sh[256];
    int t = threadIdx.x;
    int base = blockIdx.x * 1024 + t * 4;
    int s = 0;
    #pragma unroll
    for (int i = 0; i < 4; i++) { int idx = base + i; if (idx < N) s += cnt[idx]; }
    sh[t] = s;
    __syncthreads();
    for (int off = 128; off > 0; off >>= 1) {
        if (t < off) sh[t] += sh[t + off];
        __syncthreads();
    }
    if (t == 0) bsum[blockIdx.x] = sh[0];
}

__global__ void scan2_kernel(const int* __restrict__ bsum, int* bbase, int NB,
                             int* off, int N, int E) {
    __shared__ int sh[128];
    int t = threadIdx.x;
    int v = (t < NB) ? bsum[t] : 0;
    sh[t] = v;
    __syncthreads();
    #pragma unroll
    for (int d = 1; d < 128; d <<= 1) {
        int u = (t >= d) ? sh[t - d] : 0;
        __syncthreads();
        sh[t] += u;
        __syncthreads();
    }
    if (t < NB) bbase[t] = sh[t] - v;
    if (t == 0) off[N] = E;
}

__global__ void scan3_kernel(const int* __restrict__ cnt, const int* __restrict__ bbase,
                             int* off, int* cur, int N) {
    __shared__ int sh[256];
    int t = threadIdx.x;
    int base = blockIdx.x * 1024 + t * 4;
    int v[4]; int s = 0;
    #pragma unroll
    for (int i = 0; i < 4; i++) {
        int idx = base + i;
        v[i] = (idx < N) ? cnt[idx] : 0;
        s += v[i];
    }
    sh[t] = s;
    __syncthreads();
    #pragma unroll
    for (int d = 1; d < 256; d <<= 1) {
        int u = (t >= d) ? sh[t - d] : 0;
        __syncthreads();
        sh[t] += u;
        __syncthreads();
    }
    int run = bbase[blockIdx.x] + sh[t] - s;
    #pragma unroll
    for (int i = 0; i < 4; i++) {
        int idx = base + i;
        if (idx < N) { off[idx] = run; cur[idx] = run; run += v[i]; }
    }
}

__global__ void fill_kernel(const int* __restrict__ ei, int* cur, int* csr, int E) {
    int e = blockIdx.x * blockDim.x + threadIdx.x;
    if (e < E) {
        int d = ei[E + e];
        int p = atomicAdd(&cur[d], 1);
        csr[p] = ei[e];
    }
}

// ================= aggregation: agg[n] = x[n] + sum_{s in csr[n]} x[s] ======
__global__ void agg_csr_kernel(const float* __restrict__ x,
                               const int* __restrict__ off,
                               const int* __restrict__ csr,
                               float* __restrict__ agg, int M) {
    int warp = (blockIdx.x * blockDim.x + threadIdx.x) >> 5;
    int lane = threadIdx.x & 31;
    if (warp >= M) return;
    int beg = off[warp], end = off[warp + 1];
    const float4* xr = reinterpret_cast<const float4*>(x);
    float4 sum = xr[(size_t)warp * 32 + lane];
    int e = beg;
    for (; e + 3 < end; e += 4) {
        int s0 = csr[e], s1 = csr[e + 1], s2 = csr[e + 2], s3 = csr[e + 3];
        float4 v0 = xr[(size_t)s0 * 32 + lane];
        float4 v1 = xr[(size_t)s1 * 32 + lane];
        float4 v2 = xr[(size_t)s2 * 32 + lane];
        float4 v3 = xr[(size_t)s3 * 32 + lane];
        sum.x += (v0.x + v1.x) + (v2.x + v3.x);
        sum.y += (v0.y + v1.y) + (v2.y + v3.y);
        sum.z += (v0.z + v1.z) + (v2.z + v3.z);
        sum.w += (v0.w + v1.w) + (v2.w + v3.w);
    }
    for (; e < end; e++) {
        int s = csr[e];
        float4 v = xr[(size_t)s * 32 + lane];
        sum.x += v.x; sum.y += v.y; sum.z += v.z; sum.w += v.w;
    }
    reinterpret_cast<float4*>(agg)[(size_t)warp * 32 + lane] = sum;
}

// ---------------- W prep: W[k][n] fp32 -> W^T hi/lo bf16 padded images ------
struct WPtrs { const float* p[6]; };
__global__ void wprep_kernel(WPtrs wp, __nv_bfloat16* img) {
    int t = blockIdx.x * blockDim.x + threadIdx.x;
    if (t >= 6 * 16384) return;
    int g = t >> 14;
    int rem = t & 16383;
    int n = rem >> 7;
    int k = rem & 127;
    float w = wp.p[g][k * D + n];
    __nv_bfloat16 hi = __float2bfloat16(w);
    float r = w - __bfloat162float(hi);
    __nv_bfloat16 lo = __float2bfloat16(r);
    size_t base = (size_t)g * 2 * IMG_ELEMS;
    img[base + n * 136 + k]             = hi;
    img[base + IMG_ELEMS + n * 136 + k] = lo;
}

// ---------------- mma core: acc += Aimg @ Wimg (3-term bf16) -----------------
__device__ __forceinline__ void mma_tile(uint32_t aBase, uint32_t wBase, float acc[8][4]) {
    #pragma unroll
    for (int kc = 0; kc < 8; kc++) {
        uint32_t aHi[4], aLo[4];
        uint32_t aAddr = aBase + kc * 32;
        LDSM_X4(aHi[0], aHi[1], aHi[2], aHi[3], aAddr);
        LDSM_X4(aLo[0], aLo[1], aLo[2], aLo[3], aAddr + HALF);
        #pragma unroll
        for (int nbp = 0; nbp < 4; nbp++) {
            uint32_t bAddr = wBase + nbp * (16 * ROWB) + kc * 32;
            uint32_t bh0, bh1, bh2, bh3, bl0, bl1, bl2, bl3;
            LDSM_X4(bh0, bh1, bh2, bh3, bAddr);
            LDSM_X4(bl0, bl1, bl2, bl3, bAddr + HALF);
            mma_bf16(acc[2 * nbp],     aHi, bh0, bh1);
            mma_bf16(acc[2 * nbp],     aHi, bl0, bl1);
            mma_bf16(acc[2 * nbp],     aLo, bh0, bh1);
            mma_bf16(acc[2 * nbp + 1], aHi, bh2, bh3);
            mma_bf16(acc[2 * nbp + 1], aHi, bl2, bl3);
            mma_bf16(acc[2 * nbp + 1], aLo, bh2, bh3);
        }
    }
}

// ---------------- fused layer: out = relu(relu(agg@W1+b1)@W2+b2) -------------
// Persistent, 512 threads (16 warps), 1 CTA/SM, tile = 128 rows x 128 cols.
// Warp grid 8x2: wg_row = wid&7 (16 rows), wg_col = wid>>3 (64 cols).
__global__ __launch_bounds__(512, 1) void layer_kernel(
    const float* __restrict__ A,
    const __nv_bfloat16* __restrict__ W1img, const __nv_bfloat16* __restrict__ W2img,
    const float* __restrict__ b1, const float* __restrict__ b2,
    float* __restrict__ C, int M, int nt) {
    extern __shared__ char smem[];
    uint32_t sb = smem_u32(smem);
    int tid = threadIdx.x, wid = tid >> 5, lane = tid & 31;
    int wg_row = wid & 7, wg_col = wid >> 3;

    // ---- one-time: W1 + W2 (2 x 69632 B) + biases ----
    {
        const char* s1 = reinterpret_cast<const char*>(W1img);
        const char* s2 = reinterpret_cast<const char*>(W2img);
        #pragma unroll
        for (int i = 0; i < 17; i++) {
            uint32_t c = (uint32_t)(tid + i * 512);        // 0..8703
            if (c < 4352) {
                uint32_t o = c * 16;
                CP_ASYNC16(sb + OFF_W1 + o, s1 + o);
            } else {
                uint32_t o = (c - 4352) * 16;
                CP_ASYNC16(sb + OFF_W2 + o, s2 + o);
            }
        }
    }
    if (tid < 32)
        reinterpret_cast<float4*>(smem + OFF_B1)[tid] =
            reinterpret_cast<const float4*>(b1)[tid];
    else if (tid < 64)
        reinterpret_cast<float4*>(smem + OFF_B2)[tid - 32] =
            reinterpret_cast<const float4*>(b2)[tid - 32];
    CP_WAIT();
    __syncthreads();

    const float* sB1 = reinterpret_cast<const float*>(smem + OFF_B1);
    const float* sB2 = reinterpret_cast<const float*>(smem + OFF_B2);
    uint32_t aBase = sb + OFF_AHI + (wg_row * 16 + (lane & 15)) * ROWB + (lane >> 4) * 16;
    uint32_t w1Base = sb + OFF_W1
                    + (wg_col * 64 + ((lane >> 4) << 3) + (lane & 7)) * ROWB
                    + ((lane >> 3) & 1) * 16;
    uint32_t w2Base = w1Base + (OFF_W2 - OFF_W1);

    for (int t = blockIdx.x; t < nt; t += gridDim.x) {
        int row0 = t << 7;

        // ---- convert agg tile: warp wid -> rows wid*8 .. +8 ----
        #pragma unroll
        for (int i = 0; i < 8; i++) {
            int trow = wid * 8 + i;
            int grow = row0 + trow;
            uint32_t hi0 = 0, hi1 = 0, lo0 = 0, lo1 = 0;
            if (grow < M) {
                float4 v = reinterpret_cast<const float4*>(A + (size_t)grow * D)[lane];
                split2(v.x, v.y, hi0, lo0);
                split2(v.z, v.w, hi1, lo1);
            }
            uint32_t o = (uint32_t)trow * ROWB + (uint32_t)lane * 8;
            *reinterpret_cast<uint2*>(smem + OFF_AHI + o) = make_uint2(hi0, hi1);
            *reinterpret_cast<uint2*>(smem + OFF_ALO + o) = make_uint2(lo0, lo1);
        }
        __syncthreads();

        // ---- GEMM1 ----
        float acc[8][4];
        #pragma unroll
        for (int nb = 0; nb < 8; nb++)
            #pragma unroll
            for (int j = 0; j < 4; j++) acc[nb][j] = 0.0f;
        mma_tile(aBase, w1Base, acc);
        __syncthreads();   // everyone done reading A image before overwrite

        // ---- h = relu(acc + b1), split to bf16 hi/lo, store into image ----
        {
            int trow0 = wg_row * 16 + (lane >> 2);
            int trow1 = trow0 + 8;
            #pragma unroll
            for (int nb = 0; nb < 8; nb++) {
                int cb = wg_col * 64 + nb * 8 + (lane & 3) * 2;
                float bb0 = sB1[cb], bb1 = sB1[cb + 1];
                float o0 = fmaxf(acc[nb][0] + bb0, 0.f);
                float o1 = fmaxf(acc[nb][1] + bb1, 0.f);
                float o2 = fmaxf(acc[nb][2] + bb0, 0.f);
                float o3 = fmaxf(acc[nb][3] + bb1, 0.f);
                uint32_t hi, lo;
                uint32_t oa = (uint32_t)trow0 * ROWB + (uint32_t)cb * 2;
                split2(o0, o1, hi, lo);
                *reinterpret_cast<uint32_t*>(smem + OFF_AHI + oa) = hi;
                *reinterpret_cast<uint32_t*>(smem + OFF_ALO + oa) = lo;
                uint32_t ob = (uint32_t)trow1 * ROWB + (uint32_t)cb * 2;
                split2(o2, o3, hi, lo);
                *reinterpret_cast<uint32_t*>(smem + OFF_AHI + ob) = hi;
                *reinterpret_cast<uint32_t*>(smem + OFF_ALO + ob) = lo;
            }
        }
        __syncthreads();

        // ---- GEMM2 ----
        #pragma unroll
        for (int nb = 0; nb < 8; nb++)
            #pragma unroll
            for (int j = 0; j < 4; j++) acc[nb][j] = 0.0f;
        mma_tile(aBase, w2Base, acc);

        // ---- epilogue: out = relu(acc + b2) ----
        int r0 = row0 + wg_row * 16 + (lane >> 2);
        int r1 = r0 + 8;
        #pragma unroll
        for (int nb = 0; nb < 8; nb++) {
            int cb = wg_col * 64 + nb * 8 + (lane & 3) * 2;
            float bb0 = sB2[cb], bb1 = sB2[cb + 1];
            if (r0 < M) {
                float2 o;
                o.x = fmaxf(acc[nb][0] + bb0, 0.f);
                o.y = fmaxf(acc[nb][1] + bb1, 0.f);
                *reinterpret_cast<float2*>(C + (size_t)r0 * D + cb) = o;
            }
            if (r1 < M) {
                float2 o;
                o.x = fmaxf(acc[nb][2] + bb0, 0.f);
                o.y = fmaxf(acc[nb][3] + bb1, 0.f);
                *reinterpret_cast<float2*>(C + (size_t)r1 * D + cb) = o;
            }
        }
        __syncthreads();   // all reads of A/h image done before next convert
    }
}

extern "C" void kernel_launch(void* const* d_in, const int* in_sizes, int n_in,
                              void* d_out, int out_size) {
    const float* x  = (const float*)d_in[0];
    const int*   ei = (const int*)d_in[1];   // int32 (JAX x64 disabled)
    const float* W1[3] = {(const float*)d_in[2],  (const float*)d_in[6],  (const float*)d_in[10]};
    const float* b1[3] = {(const float*)d_in[3],  (const float*)d_in[7],  (const float*)d_in[11]};
    const float* W2[3] = {(const float*)d_in[4],  (const float*)d_in[8],  (const float*)d_in[12]};
    const float* b2[3] = {(const float*)d_in[5],  (const float*)d_in[9],  (const float*)d_in[13]};

    int M = in_sizes[0] / D;
    int E = in_sizes[1] / 2;

    float *agg, *t;
    __nv_bfloat16* wimg;
    int *cnt, *off, *cur, *csr, *bsum, *bbase;
    cudaGetSymbolAddress((void**)&agg,   g_agg);
    cudaGetSymbolAddress((void**)&t,     g_t);
    cudaGetSymbolAddress((void**)&wimg,  g_Wimg);
    cudaGetSymbolAddress((void**)&cnt,   g_cnt);
    cudaGetSymbolAddress((void**)&off,   g_off);
    cudaGetSymbolAddress((void**)&cur,   g_cur);
    cudaGetSymbolAddress((void**)&csr,   g_csr);
    cudaGetSymbolAddress((void**)&bsum,  g_bsum);
    cudaGetSymbolAddress((void**)&bbase, g_bbase);

    cudaFuncSetAttribute(layer_kernel, cudaFuncAttributeMaxDynamicSharedMemorySize, SMEM_TOTAL);

    // W images (order: W1_0, W2_0, W1_1, W2_1, W1_2, W2_2)
    WPtrs wp;
    wp.p[0] = W1[0]; wp.p[1] = W2[0];
    wp.p[2] = W1[1]; wp.p[3] = W2[1];
    wp.p[4] = W1[2]; wp.p[5] = W2[2];
    wprep_kernel<<<(6 * 16384 + 255) / 256, 256>>>(wp, wimg);

    // CSR build (edges identical across layers)
    int NB = (M + 1023) / 1024;
    zero_cnt_kernel<<<(M + 255) / 256, 256>>>(cnt, M);
    hist_kernel<<<(E + 255) / 256, 256>>>(ei, cnt, E);
    scan1_kernel<<<NB, 256>>>(cnt, bsum, M);
    scan2_kernel<<<1, 128>>>(bsum, bbase, NB, off, M, E);
    scan3_kernel<<<NB, 256>>>(cnt, bbase, off, cur, M);
    fill_kernel<<<(E + 255) / 256, 256>>>(ei, cur, csr, E);

    int aggBlocks = (M * 32 + 255) / 256;
    int nt = (M + 127) / 128;
    int grid = (nt < 152) ? nt : 152;

    const float* curx = x;
    float* outs[3] = {t, t, (float*)d_out};

    for (int l = 0; l < 3; l++) {
        agg_csr_kernel<<<aggBlocks, 256>>>(curx, off, csr, agg, M);
        layer_kernel<<<grid, 512, SMEM_TOTAL>>>(
            agg,
            wimg + (size_t)(2 * l) * 2 * IMG_ELEMS,
            wimg + (size_t)(2 * l + 1) * 2 * IMG_ELEMS,
            b1[l], b2[l], outs[l], M, nt);
        curx = outs[l];
    }
}

// round 12
// speedup vs baseline: 1.0010x; 1.0010x over previous
#include <cuda_runtime.h>
#include <cuda_bf16.h>
#include <cstdint>

#define D 128
#define MAXN 100000
#define MAXE 1600000

// ---------------- device scratch (allocation-free rule) --------------------
__device__ float g_agg[(size_t)MAXN * D];
__device__ float g_h  [(size_t)MAXN * D];
__device__ float g_t  [(size_t)MAXN * D];
// CSR scratch
__device__ int g_cnt[MAXN];
__device__ int g_off[MAXN + 1];
__device__ int g_cur[MAXN];
__device__ int g_csr[MAXE];
__device__ int g_bsum[128];
__device__ int g_bbase[128];
// 6 GEMMs x (hi + lo) W^T images, padded row-major [n][136] bf16
#define IMG_ELEMS 17408            // 128 * 136
__device__ __nv_bfloat16 g_Wimg[6 * 2 * IMG_ELEMS];

// ---------------- smem layout for gemm (bytes) ------------------------------
#define ROWB      272              // 136 bf16 per row
#define IMG_BYTES 34816            // 128 * 272 (W image) ; A image = 64*272
#define OFF_WHI   0
#define OFF_WLO   34816
#define OFF_AHI   69632
#define OFF_ALO   87040
#define OFF_BIAS  104448
#define SMEM_TOTAL 104960

#define GEMM_GRID 304              // 2 CTAs x 152 SMs, persistent

__device__ __forceinline__ uint32_t smem_u32(const void* p) {
    uint32_t a;
    asm("{ .reg .u64 t; cvta.to.shared.u64 t, %1; cvt.u32.u64 %0, t; }" : "=r"(a) : "l"(p));
    return a;
}

#define LDSM_X4(r0, r1, r2, r3, addr) \
    asm volatile("ldmatrix.sync.aligned.m8n8.x4.shared.b16 {%0,%1,%2,%3}, [%4];" \
                 : "=r"(r0), "=r"(r1), "=r"(r2), "=r"(r3) : "r"(addr))

#define CP_ASYNC16(dst, src) \
    asm volatile("cp.async.cg.shared.global [%0], [%1], 16;" :: "r"(dst), "l"(src))
#define CP_WAIT() asm volatile("cp.async.wait_all;" ::: "memory")

__device__ __forceinline__ void mma_bf16(float* c, const uint32_t* a, uint32_t b0, uint32_t b1) {
    asm volatile(
        "mma.sync.aligned.m16n8k16.row.col.f32.bf16.bf16.f32 "
        "{%0,%1,%2,%3}, {%4,%5,%6,%7}, {%8,%9}, {%0,%1,%2,%3};"
        : "+f"(c[0]), "+f"(c[1]), "+f"(c[2]), "+f"(c[3])
        : "r"(a[0]), "r"(a[1]), "r"(a[2]), "r"(a[3]), "r"(b0), "r"(b1));
}

// hi/lo bf16 split of 2 floats -> packed bf16x2 regs
__device__ __forceinline__ void split2(float x0, float x1, uint32_t& hi, uint32_t& lo) {
    __nv_bfloat162 h = __floats2bfloat162_rn(x0, x1);
    float r0 = x0 - __bfloat162float(h.x);
    float r1 = x1 - __bfloat162float(h.y);
    __nv_bfloat162 l = __floats2bfloat162_rn(r0, r1);
    hi = *reinterpret_cast<uint32_t*>(&h);
    lo = *reinterpret_cast<uint32_t*>(&l);
}

// ================= CSR build =================================================
__global__ void zero_cnt_kernel(int* cnt, int N) {
    int i = blockIdx.x * blockDim.x + threadIdx.x;
    if (i < N) cnt[i] = 0;
}

__global__ void hist_kernel(const int* __restrict__ ei, int* cnt, int E) {
    int e = blockIdx.x * blockDim.x + threadIdx.x;
    if (e < E) atomicAdd(&cnt[ei[E + e]], 1);
}

__global__ void scan1_kernel(const int* __restrict__ cnt, int* bsum, int N) {
    __shared__ int sh[256];
    int t = threadIdx.x;
    int base = blockIdx.x * 1024 + t * 4;
    int s = 0;
    #pragma unroll
    for (int i = 0; i < 4; i++) { int idx = base + i; if (idx < N) s += cnt[idx]; }
    sh[t] = s;
    __syncthreads();
    for (int off = 128; off > 0; off >>= 1) {
        if (t < off) sh[t] += sh[t + off];
        __syncthreads();
    }
    if (t == 0) bsum[blockIdx.x] = sh[0];
}

__global__ void scan2_kernel(const int* __restrict__ bsum, int* bbase, int NB,
                             int* off, int N, int E) {
    __shared__ int sh[128];
    int t = threadIdx.x;
    int v = (t < NB) ? bsum[t] : 0;
    sh[t] = v;
    __syncthreads();
    #pragma unroll
    for (int d = 1; d < 128; d <<= 1) {
        int u = (t >= d) ? sh[t - d] : 0;
        __syncthreads();
        sh[t] += u;
        __syncthreads();
    }
    if (t < NB) bbase[t] = sh[t] - v;
    if (t == 0) off[N] = E;
}

__global__ void scan3_kernel(const int* __restrict__ cnt, const int* __restrict__ bbase,
                             int* off, int* cur, int N) {
    __shared__ int sh[256];
    int t = threadIdx.x;
    int base = blockIdx.x * 1024 + t * 4;
    int v[4]; int s = 0;
    #pragma unroll
    for (int i = 0; i < 4; i++) {
        int idx = base + i;
        v[i] = (idx < N) ? cnt[idx] : 0;
        s += v[i];
    }
    sh[t] = s;
    __syncthreads();
    #pragma unroll
    for (int d = 1; d < 256; d <<= 1) {
        int u = (t >= d) ? sh[t - d] : 0;
        __syncthreads();
        sh[t] += u;
        __syncthreads();
    }
    int run = bbase[blockIdx.x] + sh[t] - s;
    #pragma unroll
    for (int i = 0; i < 4; i++) {
        int idx = base + i;
        if (idx < N) { off[idx] = run; cur[idx] = run; run += v[i]; }
    }
}

__global__ void fill_kernel(const int* __restrict__ ei, int* cur, int* csr, int E) {
    int e = blockIdx.x * blockDim.x + threadIdx.x;
    if (e < E) {
        int d = ei[E + e];
        int p = atomicAdd(&cur[d], 1);
        csr[p] = ei[e];
    }
}

// ================= aggregation: agg[n] = x[n] + sum_{s in csr[n]} x[s] ======
__global__ void agg_csr_kernel(const float* __restrict__ x,
                               const int* __restrict__ off,
                               const int* __restrict__ csr,
                               float* __restrict__ agg, int M) {
    int warp = (blockIdx.x * blockDim.x + threadIdx.x) >> 5;
    int lane = threadIdx.x & 31;
    if (warp >= M) return;
    int beg = off[warp], end = off[warp + 1];
    const float4* xr = reinterpret_cast<const float4*>(x);
    float4 sum = xr[(size_t)warp * 32 + lane];
    int e = beg;
    for (; e + 3 < end; e += 4) {
        int s0 = csr[e], s1 = csr[e + 1], s2 = csr[e + 2], s3 = csr[e + 3];
        float4 v0 = xr[(size_t)s0 * 32 + lane];
        float4 v1 = xr[(size_t)s1 * 32 + lane];
        float4 v2 = xr[(size_t)s2 * 32 + lane];
        float4 v3 = xr[(size_t)s3 * 32 + lane];
        sum.x += (v0.x + v1.x) + (v2.x + v3.x);
        sum.y += (v0.y + v1.y) + (v2.y + v3.y);
        sum.z += (v0.z + v1.z) + (v2.z + v3.z);
        sum.w += (v0.w + v1.w) + (v2.w + v3.w);
    }
    for (; e < end; e++) {
        int s = csr[e];
        float4 v = xr[(size_t)s * 32 + lane];
        sum.x += v.x; sum.y += v.y; sum.z += v.z; sum.w += v.w;
    }
    reinterpret_cast<float4*>(agg)[(size_t)warp * 32 + lane] = sum;
}

// ---------------- W prep: W[k][n] fp32 -> W^T hi/lo bf16 padded images ------
struct WPtrs { const float* p[6]; };
__global__ void wprep_kernel(WPtrs wp, __nv_bfloat16* img) {
    int t = blockIdx.x * blockDim.x + threadIdx.x;
    if (t >= 6 * 16384) return;
    int g = t >> 14;
    int rem = t & 16383;
    int n = rem >> 7;
    int k = rem & 127;
    float w = wp.p[g][k * D + n];
    __nv_bfloat16 hi = __float2bfloat16(w);
    float r = w - __bfloat162float(hi);
    __nv_bfloat16 lo = __float2bfloat16(r);
    size_t base = (size_t)g * 2 * IMG_ELEMS;
    img[base + n * 136 + k]             = hi;
    img[base + IMG_ELEMS + n * 136 + k] = lo;
}

// ---------------- GEMM: persistent, warp tile 32x32 (2x4 warp grid) ---------
// Grid 304 (2 CTAs/SM), 256 threads / 8 warps, tile 64x128 per iteration.
// wg_row = wid&1 (32 rows), wg_col = wid>>1 (32 cols).
// 4 warps sharing a 32-row group split its convert (8 rows each) and sync on
// named barrier (1+wg_row, 128 threads). No block-wide sync in the loop.
__global__ __launch_bounds__(256, 2) void gemm_mma_kernel(
    const float* __restrict__ A, const __nv_bfloat16* __restrict__ Wimg,
    const float* __restrict__ bias, float* __restrict__ C, int M, int nt) {
    extern __shared__ char smem[];
    uint32_t sb = smem_u32(smem);
    int tid = threadIdx.x, wid = tid >> 5, lane = tid & 31;
    int wg_row = wid & 1, wg_col = wid >> 1;

    // ---- one-time: W hi+lo (69632 B) + bias ----
    {
        const char* src = reinterpret_cast<const char*>(Wimg);
        #pragma unroll
        for (int i = 0; i < 17; i++) {
            uint32_t o = (uint32_t)(tid + i * 256) * 16;
            CP_ASYNC16(sb + OFF_WHI + o, src + o);
        }
    }
    if (tid < 32)
        reinterpret_cast<float4*>(smem + OFF_BIAS)[tid] =
            reinterpret_cast<const float4*>(bias)[tid];
    CP_WAIT();
    __syncthreads();

    const float* sBias = reinterpret_cast<const float*>(smem + OFF_BIAS);
    // A base: rows wg_row*32 + (lane&15); (lane>>4) -> k+8. m-block 1 at +16*ROWB.
    uint32_t aBase = sb + OFF_AHI + (wg_row * 32 + (lane & 15)) * ROWB + (lane >> 4) * 16;
    // B base: n rows wg_col*32 + ((lane>>4)<<3) + (lane&7); (lane>>3)&1 -> k+8.
    // First X4 covers n-blocks 0,1; second X4 (+16*ROWB) covers n-blocks 2,3.
    uint32_t wBase = sb + OFF_WHI
                   + (wg_col * 32 + ((lane >> 4) << 3) + (lane & 7)) * ROWB
                   + ((lane >> 3) & 1) * 16;
    int convBase = wg_row * 32 + wg_col * 8;   // 4 warps split 32 rows: 8 each

    for (int t = blockIdx.x; t < nt; t += gridDim.x) {
        int row0 = t << 6;

        // ---- convert this quarter's 8 A rows ----
        #pragma unroll
        for (int i = 0; i < 8; i++) {
            int trow = convBase + i;
            int grow = row0 + trow;
            uint32_t hi0 = 0, hi1 = 0, lo0 = 0, lo1 = 0;
            if (grow < M) {
                float4 v = reinterpret_cast<const float4*>(A + (size_t)grow * D)[lane];
                split2(v.x, v.y, hi0, lo0);
                split2(v.z, v.w, hi1, lo1);
            }
            uint32_t o = (uint32_t)trow * ROWB + (uint32_t)lane * 8;
            *reinterpret_cast<uint2*>(smem + OFF_AHI + o) = make_uint2(hi0, hi1);
            *reinterpret_cast<uint2*>(smem + OFF_ALO + o) = make_uint2(lo0, lo1);
        }
        asm volatile("bar.sync %0, 128;" :: "r"(1 + wg_row) : "memory");

        // ---- mma loop: warp tile 32x32 ----
        float acc[2][4][4];
        #pragma unroll
        for (int m = 0; m < 2; m++)
            #pragma unroll
            for (int nb = 0; nb < 4; nb++)
                #pragma unroll
                for (int j = 0; j < 4; j++) acc[m][nb][j] = 0.0f;

        #pragma unroll
        for (int kc = 0; kc < 8; kc++) {
            uint32_t aHi[2][4], aLo[2][4];
            uint32_t aAddr = aBase + kc * 32;
            LDSM_X4(aHi[0][0], aHi[0][1], aHi[0][2], aHi[0][3], aAddr);
            LDSM_X4(aHi[1][0], aHi[1][1], aHi[1][2], aHi[1][3], aAddr + 16 * ROWB);
            LDSM_X4(aLo[0][0], aLo[0][1], aLo[0][2], aLo[0][3], aAddr + (OFF_ALO - OFF_AHI));
            LDSM_X4(aLo[1][0], aLo[1][1], aLo[1][2], aLo[1][3], aAddr + (OFF_ALO - OFF_AHI) + 16 * ROWB);

            uint32_t bAddr = wBase + kc * 32;
            uint32_t bh[8], bl[8];
            LDSM_X4(bh[0], bh[1], bh[2], bh[3], bAddr);                 // n-blocks 0,1
            LDSM_X4(bh[4], bh[5], bh[6], bh[7], bAddr + 16 * ROWB);     // n-blocks 2,3
            LDSM_X4(bl[0], bl[1], bl[2], bl[3], bAddr + IMG_BYTES);
            LDSM_X4(bl[4], bl[5], bl[6], bl[7], bAddr + IMG_BYTES + 16 * ROWB);

            #pragma unroll
            for (int m = 0; m < 2; m++) {
                #pragma unroll
                for (int nb = 0; nb < 4; nb++) {
                    mma_bf16(acc[m][nb], aHi[m], bh[2 * nb], bh[2 * nb + 1]);
                    mma_bf16(acc[m][nb], aHi[m], bl[2 * nb], bl[2 * nb + 1]);
                    mma_bf16(acc[m][nb], aLo[m], bh[2 * nb], bh[2 * nb + 1]);
                }
            }
        }

        // WAR: group done reading A before next iteration's convert overwrites
        asm volatile("bar.sync %0, 128;" :: "r"(1 + wg_row) : "memory");

        // ---- epilogue ----
        #pragma unroll
        for (int m = 0; m < 2; m++) {
            int r0 = row0 + wg_row * 32 + m * 16 + (lane >> 2);
            int r1 = r0 + 8;
            #pragma unroll
            for (int nb = 0; nb < 4; nb++) {
                int cb = wg_col * 32 + nb * 8 + (lane & 3) * 2;
                float b0 = sBias[cb], b1 = sBias[cb + 1];
                if (r0 < M) {
                    float2 o;
                    o.x = fmaxf(acc[m][nb][0] + b0, 0.f);
                    o.y = fmaxf(acc[m][nb][1] + b1, 0.f);
                    *reinterpret_cast<float2*>(C + (size_t)r0 * D + cb) = o;
                }
                if (r1 < M) {
                    float2 o;
                    o.x = fmaxf(acc[m][nb][2] + b0, 0.f);
                    o.y = fmaxf(acc[m][nb][3] + b1, 0.f);
                    *reinterpret_cast<float2*>(C + (size_t)r1 * D + cb) = o;
                }
            }
        }
    }
}

extern "C" void kernel_launch(void* const* d_in, const int* in_sizes, int n_in,
                              void* d_out, int out_size) {
    const float* x  = (const float*)d_in[0];
    const int*   ei = (const int*)d_in[1];   // int32 (JAX x64 disabled)
    const float* W1[3] = {(const float*)d_in[2],  (const float*)d_in[6],  (const float*)d_in[10]};
    const float* b1[3] = {(const float*)d_in[3],  (const float*)d_in[7],  (const float*)d_in[11]};
    const float* W2[3] = {(const float*)d_in[4],  (const float*)d_in[8],  (const float*)d_in[12]};
    const float* b2[3] = {(const float*)d_in[5],  (const float*)d_in[9],  (const float*)d_in[13]};

    int M = in_sizes[0] / D;
    int E = in_sizes[1] / 2;

    float *agg, *h, *t;
    __nv_bfloat16* wimg;
    int *cnt, *off, *cur, *csr, *bsum, *bbase;
    cudaGetSymbolAddress((void**)&agg,   g_agg);
    cudaGetSymbolAddress((void**)&h,     g_h);
    cudaGetSymbolAddress((void**)&t,     g_t);
    cudaGetSymbolAddress((void**)&wimg,  g_Wimg);
    cudaGetSymbolAddress((void**)&cnt,   g_cnt);
    cudaGetSymbolAddress((void**)&off,   g_off);
    cudaGetSymbolAddress((void**)&cur,   g_cur);
    cudaGetSymbolAddress((void**)&csr,   g_csr);
    cudaGetSymbolAddress((void**)&bsum,  g_bsum);
    cudaGetSymbolAddress((void**)&bbase, g_bbase);

    cudaFuncSetAttribute(gemm_mma_kernel, cudaFuncAttributeMaxDynamicSharedMemorySize, SMEM_TOTAL);

    // W images (order: W1_0, W2_0, W1_1, W2_1, W1_2, W2_2)
    WPtrs wp;
    wp.p[0] = W1[0]; wp.p[1] = W2[0];
    wp.p[2] = W1[1]; wp.p[3] = W2[1];
    wp.p[4] = W1[2]; wp.p[5] = W2[2];
    wprep_kernel<<<(6 * 16384 + 255) / 256, 256>>>(wp, wimg);

    // CSR build (edges identical across layers)
    int NB = (M + 1023) / 1024;
    zero_cnt_kernel<<<(M + 255) / 256, 256>>>(cnt, M);
    hist_kernel<<<(E + 255) / 256, 256>>>(ei, cnt, E);
    scan1_kernel<<<NB, 256>>>(cnt, bsum, M);
    scan2_kernel<<<1, 128>>>(bsum, bbase, NB, off, M, E);
    scan3_kernel<<<NB, 256>>>(cnt, bbase, off, cur, M);
    fill_kernel<<<(E + 255) / 256, 256>>>(ei, cur, csr, E);

    int aggBlocks = (M * 32 + 255) / 256;
    int nt = (M + 63) / 64;
    int gemmGrid = (nt < GEMM_GRID) ? nt : GEMM_GRID;

    const float* curx = x;
    float* outs[3] = {t, t, (float*)d_out};

    for (int l = 0; l < 3; l++) {
        agg_csr_kernel<<<aggBlocks, 256>>>(curx, off, csr, agg, M);
        gemm_mma_kernel<<<gemmGrid, 256, SMEM_TOTAL>>>(
            agg, wimg + (size_t)(2 * l) * 2 * IMG_ELEMS, b1[l], h, M, nt);
        gemm_mma_kernel<<<gemmGrid, 256, SMEM_TOTAL>>>(
            h, wimg + (size_t)(2 * l + 1) * 2 * IMG_ELEMS, b2[l], outs[l], M, nt);
        curx = outs[l];
    }
}

// round 13
// speedup vs baseline: 1.0380x; 1.0370x over previous
#include <cuda_runtime.h>
#include <cuda_bf16.h>
#include <cstdint>

#define D 128
#define MAXN 100000
#define MAXE 1600000

// ---------------- device scratch (allocation-free rule) --------------------
__device__ float g_agg[(size_t)MAXN * D];
__device__ float g_h  [(size_t)MAXN * D];
__device__ float g_t  [(size_t)MAXN * D];
// CSR scratch
__device__ int g_cnt[MAXN];
__device__ int g_off[MAXN + 1];
__device__ int g_cur[MAXN];
__device__ int g_csr[MAXE];
__device__ int g_bsum[128];
__device__ int g_bbase[128];
// 6 GEMMs x (hi + lo) W^T images, padded row-major [n][136] bf16
#define IMG_ELEMS 17408            // 128 * 136
__device__ __nv_bfloat16 g_Wimg[6 * 2 * IMG_ELEMS];

// ---------------- smem layout for gemm (bytes) ------------------------------
#define ROWB      272              // 136 bf16 per row
#define IMG_BYTES 34816            // 128 * 272 (W image) ; A image = 64*272
#define OFF_WHI   0
#define OFF_WLO   34816
#define OFF_AHI   69632
#define OFF_ALO   87040
#define OFF_BIAS  104448
#define SMEM_TOTAL 104960

#define GEMM_GRID 304              // 2 CTAs x 152 SMs, persistent

__device__ __forceinline__ uint32_t smem_u32(const void* p) {
    uint32_t a;
    asm("{ .reg .u64 t; cvta.to.shared.u64 t, %1; cvt.u32.u64 %0, t; }" : "=r"(a) : "l"(p));
    return a;
}

#define LDSM_X4(r0, r1, r2, r3, addr) \
    asm volatile("ldmatrix.sync.aligned.m8n8.x4.shared.b16 {%0,%1,%2,%3}, [%4];" \
                 : "=r"(r0), "=r"(r1), "=r"(r2), "=r"(r3) : "r"(addr))

#define CP_ASYNC16(dst, src) \
    asm volatile("cp.async.cg.shared.global [%0], [%1], 16;" :: "r"(dst), "l"(src))
#define CP_WAIT() asm volatile("cp.async.wait_all;" ::: "memory")

__device__ __forceinline__ void mma_bf16(float* c, const uint32_t* a, uint32_t b0, uint32_t b1) {
    asm volatile(
        "mma.sync.aligned.m16n8k16.row.col.f32.bf16.bf16.f32 "
        "{%0,%1,%2,%3}, {%4,%5,%6,%7}, {%8,%9}, {%0,%1,%2,%3};"
        : "+f"(c[0]), "+f"(c[1]), "+f"(c[2]), "+f"(c[3])
        : "r"(a[0]), "r"(a[1]), "r"(a[2]), "r"(a[3]), "r"(b0), "r"(b1));
}

// hi/lo bf16 split of 2 floats -> packed bf16x2 regs
__device__ __forceinline__ void split2(float x0, float x1, uint32_t& hi, uint32_t& lo) {
    __nv_bfloat162 h = __floats2bfloat162_rn(x0, x1);
    float r0 = x0 - __bfloat162float(h.x);
    float r1 = x1 - __bfloat162float(h.y);
    __nv_bfloat162 l = __floats2bfloat162_rn(r0, r1);
    hi = *reinterpret_cast<uint32_t*>(&h);
    lo = *reinterpret_cast<uint32_t*>(&l);
}

// ================= CSR build =================================================
__global__ void zero_cnt_kernel(int* cnt, int N) {
    int i = blockIdx.x * blockDim.x + threadIdx.x;
    if (i < N) cnt[i] = 0;
}

__global__ void hist_kernel(const int* __restrict__ ei, int* cnt, int E) {
    int e = blockIdx.x * blockDim.x + threadIdx.x;
    if (e < E) atomicAdd(&cnt[ei[E + e]], 1);
}

__global__ void scan1_kernel(const int* __restrict__ cnt, int* bsum, int N) {
    __shared__ int sh[256];
    int t = threadIdx.x;
    int base = blockIdx.x * 1024 + t * 4;
    int s = 0;
    #pragma unroll
    for (int i = 0; i < 4; i++) { int idx = base + i; if (idx < N) s += cnt[idx]; }
    sh[t] = s;
    __syncthreads();
    for (int off = 128; off > 0; off >>= 1) {
        if (t < off) sh[t] += sh[t + off];
        __syncthreads();
    }
    if (t == 0) bsum[blockIdx.x] = sh[0];
}

__global__ void scan2_kernel(const int* __restrict__ bsum, int* bbase, int NB,
                             int* off, int N, int E) {
    __shared__ int sh[128];
    int t = threadIdx.x;
    int v = (t < NB) ? bsum[t] : 0;
    sh[t] = v;
    __syncthreads();
    #pragma unroll
    for (int d = 1; d < 128; d <<= 1) {
        int u = (t >= d) ? sh[t - d] : 0;
        __syncthreads();
        sh[t] += u;
        __syncthreads();
    }
    if (t < NB) bbase[t] = sh[t] - v;
    if (t == 0) off[N] = E;
}

__global__ void scan3_kernel(const int* __restrict__ cnt, const int* __restrict__ bbase,
                             int* off, int* cur, int N) {
    __shared__ int sh[256];
    int t = threadIdx.x;
    int base = blockIdx.x * 1024 + t * 4;
    int v[4]; int s = 0;
    #pragma unroll
    for (int i = 0; i < 4; i++) {
        int idx = base + i;
        v[i] = (idx < N) ? cnt[idx] : 0;
        s += v[i];
    }
    sh[t] = s;
    __syncthreads();
    #pragma unroll
    for (int d = 1; d < 256; d <<= 1) {
        int u = (t >= d) ? sh[t - d] : 0;
        __syncthreads();
        sh[t] += u;
        __syncthreads();
    }
    int run = bbase[blockIdx.x] + sh[t] - s;
    #pragma unroll
    for (int i = 0; i < 4; i++) {
        int idx = base + i;
        if (idx < N) { off[idx] = run; cur[idx] = run; run += v[i]; }
    }
}

__global__ void fill_kernel(const int* __restrict__ ei, int* cur, int* csr, int E) {
    int e = blockIdx.x * blockDim.x + threadIdx.x;
    if (e < E) {
        int d = ei[E + e];
        int p = atomicAdd(&cur[d], 1);
        csr[p] = ei[e];
    }
}

// ================= aggregation: agg[n] = x[n] + sum_{s in csr[n]} x[s] ======
// One warp per node; lane owns one float4. Unroll 8 edges for MLP=8.
__global__ void agg_csr_kernel(const float* __restrict__ x,
                               const int* __restrict__ off,
                               const int* __restrict__ csr,
                               float* __restrict__ agg, int M) {
    int warp = (blockIdx.x * blockDim.x + threadIdx.x) >> 5;
    int lane = threadIdx.x & 31;
    if (warp >= M) return;
    int beg = off[warp], end = off[warp + 1];
    const float4* xr = reinterpret_cast<const float4*>(x);
    float4 sum = xr[(size_t)warp * 32 + lane];
    int e = beg;
    for (; e + 7 < end; e += 8) {
        int s0 = csr[e],     s1 = csr[e + 1], s2 = csr[e + 2], s3 = csr[e + 3];
        int s4 = csr[e + 4], s5 = csr[e + 5], s6 = csr[e + 6], s7 = csr[e + 7];
        float4 v0 = xr[(size_t)s0 * 32 + lane];
        float4 v1 = xr[(size_t)s1 * 32 + lane];
        float4 v2 = xr[(size_t)s2 * 32 + lane];
        float4 v3 = xr[(size_t)s3 * 32 + lane];
        float4 v4 = xr[(size_t)s4 * 32 + lane];
        float4 v5 = xr[(size_t)s5 * 32 + lane];
        float4 v6 = xr[(size_t)s6 * 32 + lane];
        float4 v7 = xr[(size_t)s7 * 32 + lane];
        sum.x += ((v0.x + v1.x) + (v2.x + v3.x)) + ((v4.x + v5.x) + (v6.x + v7.x));
        sum.y += ((v0.y + v1.y) + (v2.y + v3.y)) + ((v4.y + v5.y) + (v6.y + v7.y));
        sum.z += ((v0.z + v1.z) + (v2.z + v3.z)) + ((v4.z + v5.z) + (v6.z + v7.z));
        sum.w += ((v0.w + v1.w) + (v2.w + v3.w)) + ((v4.w + v5.w) + (v6.w + v7.w));
    }
    for (; e < end; e++) {
        int s = csr[e];
        float4 v = xr[(size_t)s * 32 + lane];
        sum.x += v.x; sum.y += v.y; sum.z += v.z; sum.w += v.w;
    }
    reinterpret_cast<float4*>(agg)[(size_t)warp * 32 + lane] = sum;
}

// ---------------- W prep: W[k][n] fp32 -> W^T hi/lo bf16 padded images ------
struct WPtrs { const float* p[6]; };
__global__ void wprep_kernel(WPtrs wp, __nv_bfloat16* img) {
    int t = blockIdx.x * blockDim.x + threadIdx.x;
    if (t >= 6 * 16384) return;
    int g = t >> 14;
    int rem = t & 16383;
    int n = rem >> 7;
    int k = rem & 127;
    float w = wp.p[g][k * D + n];
    __nv_bfloat16 hi = __float2bfloat16(w);
    float r = w - __bfloat162float(hi);
    __nv_bfloat16 lo = __float2bfloat16(r);
    size_t base = (size_t)g * 2 * IMG_ELEMS;
    img[base + n * 136 + k]             = hi;
    img[base + IMG_ELEMS + n * 136 + k] = lo;
}

// ---------------- GEMM: persistent + register A-prefetch pipeline -----------
// Grid 304 (2 CTAs/SM), 256 threads / 8 warps, tile 64x128 per iteration.
// Warp grid 4x2 (16 rows x 64 cols). Pair {w, w+4} shares A rows, splits the
// convert (8 rows each), syncs on named barrier (1+wg_row, 64 threads).
// A rows for tile t+1 are prefetched into registers during tile t's mma.
__global__ __launch_bounds__(256, 2) void gemm_mma_kernel(
    const float* __restrict__ A, const __nv_bfloat16* __restrict__ Wimg,
    const float* __restrict__ bias, float* __restrict__ C, int M, int nt) {
    extern __shared__ char smem[];
    uint32_t sb = smem_u32(smem);
    int tid = threadIdx.x, wid = tid >> 5, lane = tid & 31;
    int wg_row = wid & 3, wg_col = wid >> 2;

    // ---- one-time: W hi+lo (69632 B) + bias ----
    {
        const char* src = reinterpret_cast<const char*>(Wimg);
        #pragma unroll
        for (int i = 0; i < 17; i++) {
            uint32_t o = (uint32_t)(tid + i * 256) * 16;
            CP_ASYNC16(sb + OFF_WHI + o, src + o);
        }
    }
    if (tid < 32)
        reinterpret_cast<float4*>(smem + OFF_BIAS)[tid] =
            reinterpret_cast<const float4*>(bias)[tid];
    CP_WAIT();
    __syncthreads();

    const float* sBias = reinterpret_cast<const float*>(smem + OFF_BIAS);
    uint32_t aBase = sb + OFF_AHI + (wg_row * 16 + (lane & 15)) * ROWB + (lane >> 4) * 16;
    uint32_t wBase = sb + OFF_WHI
                   + (wg_col * 64 + ((lane >> 4) << 3) + (lane & 7)) * ROWB
                   + ((lane >> 3) & 1) * 16;
    int convBase = wg_row * 16 + wg_col * 8;   // pair splits 16 rows: 8 each

    // ---- prefetch first tile's A rows into registers ----
    float4 pf[8];
    {
        int row0 = blockIdx.x << 6;
        #pragma unroll
        for (int i = 0; i < 8; i++) {
            int grow = row0 + convBase + i;
            pf[i] = (grow < M)
                  ? reinterpret_cast<const float4*>(A + (size_t)grow * D)[lane]
                  : make_float4(0.f, 0.f, 0.f, 0.f);
        }
    }

    for (int t = blockIdx.x; t < nt; t += gridDim.x) {
        int row0 = t << 6;

        // ---- convert this pair-half's 8 A rows (from prefetched registers) ----
        #pragma unroll
        for (int i = 0; i < 8; i++) {
            int trow = convBase + i;
            uint32_t hi0, hi1, lo0, lo1;
            split2(pf[i].x, pf[i].y, hi0, lo0);
            split2(pf[i].z, pf[i].w, hi1, lo1);
            uint32_t o = (uint32_t)trow * ROWB + (uint32_t)lane * 8;
            *reinterpret_cast<uint2*>(smem + OFF_AHI + o) = make_uint2(hi0, hi1);
            *reinterpret_cast<uint2*>(smem + OFF_ALO + o) = make_uint2(lo0, lo1);
        }
        asm volatile("bar.sync %0, 64;" :: "r"(1 + wg_row) : "memory");

        // ---- prefetch next tile's A rows (latency hidden under mma) ----
        {
            int tn = t + gridDim.x;
            if (tn < nt) {
                int nrow0 = tn << 6;
                #pragma unroll
                for (int i = 0; i < 8; i++) {
                    int grow = nrow0 + convBase + i;
                    pf[i] = (grow < M)
                          ? reinterpret_cast<const float4*>(A + (size_t)grow * D)[lane]
                          : make_float4(0.f, 0.f, 0.f, 0.f);
                }
            }
        }

        // ---- mma loop ----
        float acc[8][4];
        #pragma unroll
        for (int nb = 0; nb < 8; nb++)
            #pragma unroll
            for (int j = 0; j < 4; j++) acc[nb][j] = 0.0f;

        #pragma unroll
        for (int kc = 0; kc < 8; kc++) {
            uint32_t aHi[4], aLo[4];
            uint32_t aAddr = aBase + kc * 32;
            LDSM_X4(aHi[0], aHi[1], aHi[2], aHi[3], aAddr);
            LDSM_X4(aLo[0], aLo[1], aLo[2], aLo[3], aAddr + (OFF_ALO - OFF_AHI));
            #pragma unroll
            for (int nbp = 0; nbp < 4; nbp++) {
                uint32_t bAddr = wBase + nbp * (16 * ROWB) + kc * 32;
                uint32_t bh0, bh1, bh2, bh3, bl0, bl1, bl2, bl3;
                LDSM_X4(bh0, bh1, bh2, bh3, bAddr);
                LDSM_X4(bl0, bl1, bl2, bl3, bAddr + IMG_BYTES);
                mma_bf16(acc[2 * nbp],     aHi, bh0, bh1);
                mma_bf16(acc[2 * nbp],     aHi, bl0, bl1);
                mma_bf16(acc[2 * nbp],     aLo, bh0, bh1);
                mma_bf16(acc[2 * nbp + 1], aHi, bh2, bh3);
                mma_bf16(acc[2 * nbp + 1], aHi, bl2, bl3);
                mma_bf16(acc[2 * nbp + 1], aLo, bh2, bh3);
            }
        }

        // WAR: pair done reading A before next iteration's convert overwrites
        asm volatile("bar.sync %0, 64;" :: "r"(1 + wg_row) : "memory");

        // ---- epilogue ----
        int r0 = row0 + wg_row * 16 + (lane >> 2);
        int r1 = r0 + 8;
        #pragma unroll
        for (int nb = 0; nb < 8; nb++) {
            int cb = wg_col * 64 + nb * 8 + (lane & 3) * 2;
            float b0 = sBias[cb], b1 = sBias[cb + 1];
            if (r0 < M) {
                float2 o;
                o.x = fmaxf(acc[nb][0] + b0, 0.f);
                o.y = fmaxf(acc[nb][1] + b1, 0.f);
                *reinterpret_cast<float2*>(C + (size_t)r0 * D + cb) = o;
            }
            if (r1 < M) {
                float2 o;
                o.x = fmaxf(acc[nb][2] + b0, 0.f);
                o.y = fmaxf(acc[nb][3] + b1, 0.f);
                *reinterpret_cast<float2*>(C + (size_t)r1 * D + cb) = o;
            }
        }
    }
}

extern "C" void kernel_launch(void* const* d_in, const int* in_sizes, int n_in,
                              void* d_out, int out_size) {
    const float* x  = (const float*)d_in[0];
    const int*   ei = (const int*)d_in[1];   // int32 (JAX x64 disabled)
    const float* W1[3] = {(const float*)d_in[2],  (const float*)d_in[6],  (const float*)d_in[10]};
    const float* b1[3] = {(const float*)d_in[3],  (const float*)d_in[7],  (const float*)d_in[11]};
    const float* W2[3] = {(const float*)d_in[4],  (const float*)d_in[8],  (const float*)d_in[12]};
    const float* b2[3] = {(const float*)d_in[5],  (const float*)d_in[9],  (const float*)d_in[13]};

    int M = in_sizes[0] / D;
    int E = in_sizes[1] / 2;

    float *agg, *h, *t;
    __nv_bfloat16* wimg;
    int *cnt, *off, *cur, *csr, *bsum, *bbase;
    cudaGetSymbolAddress((void**)&agg,   g_agg);
    cudaGetSymbolAddress((void**)&h,     g_h);
    cudaGetSymbolAddress((void**)&t,     g_t);
    cudaGetSymbolAddress((void**)&wimg,  g_Wimg);
    cudaGetSymbolAddress((void**)&cnt,   g_cnt);
    cudaGetSymbolAddress((void**)&off,   g_off);
    cudaGetSymbolAddress((void**)&cur,   g_cur);
    cudaGetSymbolAddress((void**)&csr,   g_csr);
    cudaGetSymbolAddress((void**)&bsum,  g_bsum);
    cudaGetSymbolAddress((void**)&bbase, g_bbase);

    cudaFuncSetAttribute(gemm_mma_kernel, cudaFuncAttributeMaxDynamicSharedMemorySize, SMEM_TOTAL);

    // W images (order: W1_0, W2_0, W1_1, W2_1, W1_2, W2_2)
    WPtrs wp;
    wp.p[0] = W1[0]; wp.p[1] = W2[0];
    wp.p[2] = W1[1]; wp.p[3] = W2[1];
    wp.p[4] = W1[2]; wp.p[5] = W2[2];
    wprep_kernel<<<(6 * 16384 + 255) / 256, 256>>>(wp, wimg);

    // CSR build (edges identical across layers)
    int NB = (M + 1023) / 1024;
    zero_cnt_kernel<<<(M + 255) / 256, 256>>>(cnt, M);
    hist_kernel<<<(E + 255) / 256, 256>>>(ei, cnt, E);
    scan1_kernel<<<NB, 256>>>(cnt, bsum, M);
    scan2_kernel<<<1, 128>>>(bsum, bbase, NB, off, M, E);
    scan3_kernel<<<NB, 256>>>(cnt, bbase, off, cur, M);
    fill_kernel<<<(E + 255) / 256, 256>>>(ei, cur, csr, E);

    int aggBlocks = (M * 32 + 255) / 256;
    int nt = (M + 63) / 64;
    int gemmGrid = (nt < GEMM_GRID) ? nt : GEMM_GRID;

    const float* curx = x;
    float* outs[3] = {t, t, (float*)d_out};

    for (int l = 0; l < 3; l++) {
        agg_csr_kernel<<<aggBlocks, 256>>>(curx, off, csr, agg, M);
        gemm_mma_kernel<<<gemmGrid, 256, SMEM_TOTAL>>>(
            agg, wimg + (size_t)(2 * l) * 2 * IMG_ELEMS, b1[l], h, M, nt);
        gemm_mma_kernel<<<gemmGrid, 256, SMEM_TOTAL>>>(
            h, wimg + (size_t)(2 * l + 1) * 2 * IMG_ELEMS, b2[l], outs[l], M, nt);
        curx = outs[l];
    }
}